// round 2
// baseline (speedup 1.0000x reference)
#include <cuda_runtime.h>

// Problem constants (fixed by the dataset instance)
#define Bc 8
#define Cc 64
#define Hc 256
#define Wc 256
// size = 4 -> 64x64 patches of 4x4; each block handles 8 patches
#define THREADS 256

__device__ __forceinline__ float sigm(float x) {
    return 1.0f / (1.0f + __expf(-x));
}

__global__ __launch_bounds__(THREADS, 3)
void ciam_fused_kernel(const float* __restrict__ x,
                       const float* __restrict__ fc_w,
                       const float* __restrict__ fc_b,
                       const float* __restrict__ c1w,
                       const float* __restrict__ c1b,
                       const float* __restrict__ c2w,
                       const float* __restrict__ c2b,
                       float* __restrict__ out)
{
    // ---- block / thread decomposition ----
    const int blk = blockIdx.x;          // 0..4095
    const int pwg = blk & 7;             // 8-patch group along W
    const int ph  = (blk >> 3) & 63;     // patch row
    const int b   = blk >> 9;            // batch

    const int t     = threadIdx.x;
    const int patch = t & 7;             // local patch id (pw = pwg*8 + patch)
    const int r     = (t >> 3) & 3;      // row within patch
    const int cb    = t >> 5;            // channel base group (c = cb + 8k)

    // ---- shared memory (~13.3 KB) ----
    __shared__ float uni[2080];          // pm[4r][64c][8p] (pad 520/row) -> gsum/gmax -> p2s/p2m
    __shared__ float mxT[8 * 68];        // per-patch channel maxes, [patch][k], padded
    __shared__ float msm[64 * 9];        // channel-attention m[c][patch], padded stride 9
    __shared__ float g1s[32 * 4];        // g1[(r,patch)][px]
    __shared__ float g2s[8];

    // ---- scalar weights (broadcast L2 reads) ----
    const float c1w0 = __ldg(c1w), c1w1 = __ldg(c1w + 1), c1b0 = __ldg(c1b);
    const float c2w0 = __ldg(c2w), c2w1 = __ldg(c2w + 1), c2b0 = __ldg(c2b);

    // ---- load tile into registers (8 x float4, coalesced) ----
    const size_t plane = (size_t)Hc * Wc;
    const float* xb = x + (size_t)b * Cc * plane;
    float* ob = out + (size_t)b * Cc * plane;
    const int rowbase = (ph * 4 + r) * Wc + pwg * 32 + patch * 4;

    float4 v[8];
    #pragma unroll
    for (int k = 0; k < 8; k++) {
        const int c = cb + 8 * k;
        v[k] = *(const float4*)(xb + (size_t)c * plane + rowbase);
    }

    // ---- per-(c, r, patch) row max -> pm (row stride 520 => conflict-free STS) ----
    float* pm = uni;                     // [r][c][p] = r*520 + c*8 + p
    #pragma unroll
    for (int k = 0; k < 8; k++) {
        float4 a = v[k];
        float rm = fmaxf(fmaxf(a.x, a.y), fmaxf(a.z, a.w));
        pm[r * 520 + (cb + 8 * k) * 8 + patch] = rm;
    }
    __syncthreads();

    // ---- reduce over r -> mxT[patch][k] (padded stride 68) ----
    #pragma unroll
    for (int i = 0; i < 2; i++) {
        const int id = t + 256 * i;      // 0..511
        const int c  = id >> 3;
        const int p  = id & 7;
        float m0 = pm[0 * 520 + c * 8 + p];
        m0 = fmaxf(m0, pm[1 * 520 + c * 8 + p]);
        m0 = fmaxf(m0, pm[2 * 520 + c * 8 + p]);
        m0 = fmaxf(m0, pm[3 * 520 + c * 8 + p]);
        mxT[p * 68 + c] = m0;
    }
    __syncthreads();

    // ---- matvec: m[c][patch] = sigmoid(mx[patch] . fc_w[c] + fc_b[c]) ----
    // 2 c-rows x 1 patch per thread; fc_w read via L1 (shared by 8 threads/row)
    {
        const int c0 = (t >> 3) * 2;     // 0..62 step 2
        const int p  = t & 7;
        float a0 = 0.f, a1 = 0.f;
        #pragma unroll
        for (int kc = 0; kc < 16; kc++) {
            const float4 w0 = __ldg((const float4*)(fc_w + c0 * 64 + kc * 4));
            const float4 w1 = __ldg((const float4*)(fc_w + (c0 + 1) * 64 + kc * 4));
            const float4 mm = *(const float4*)(mxT + p * 68 + kc * 4);
            a0 += w0.x * mm.x + w0.y * mm.y + w0.z * mm.z + w0.w * mm.w;
            a1 += w1.x * mm.x + w1.y * mm.y + w1.z * mm.z + w1.w * mm.w;
        }
        msm[c0 * 9 + p]       = sigm(a0 + __ldg(fc_b + c0));
        msm[(c0 + 1) * 9 + p] = sigm(a1 + __ldg(fc_b + c0 + 1));
    }
    __syncthreads();

    // ---- apply channel attention; per-(patch,pixel) partials over this thread's 8 channels ----
    float4 ps  = make_float4(0.f, 0.f, 0.f, 0.f);
    float4 pmx = make_float4(-3.4e38f, -3.4e38f, -3.4e38f, -3.4e38f);
    #pragma unroll
    for (int k = 0; k < 8; k++) {
        const float m = msm[(cb + 8 * k) * 9 + patch];
        v[k].x *= m; v[k].y *= m; v[k].z *= m; v[k].w *= m;
        ps.x += v[k].x; ps.y += v[k].y; ps.z += v[k].z; ps.w += v[k].w;
        pmx.x = fmaxf(pmx.x, v[k].x); pmx.y = fmaxf(pmx.y, v[k].y);
        pmx.z = fmaxf(pmx.z, v[k].z); pmx.w = fmaxf(pmx.w, v[k].w);
    }
    float* gsum = uni;                   // [cb][rp][px] : cb*128 + rp*4 + px  (1024 floats)
    float* gmax = uni + 1024;
    const int rp = t & 31;               // (r, patch)
    *(float4*)(gsum + cb * 128 + rp * 4) = ps;
    *(float4*)(gmax + cb * 128 + rp * 4) = pmx;
    __syncthreads();

    // ---- g1 per (patch, pixel): reduce over the 8 channel-base groups ----
    if (t < 128) {
        float s  = 0.f, mx = -3.4e38f;
        #pragma unroll
        for (int g = 0; g < 8; g++) {
            s  += gsum[g * 128 + t];
            mx  = fmaxf(mx, gmax[g * 128 + t]);
        }
        g1s[t] = sigm(c1w0 * (s * (1.0f / 64.0f)) + c1w1 * mx + c1b0);
    }
    __syncthreads();

    // ---- apply g1; per-patch partials over this thread's 32 values ----
    const float4 g1v = *(const float4*)(g1s + rp * 4);
    float s2 = 0.f, m2 = -3.4e38f;
    #pragma unroll
    for (int k = 0; k < 8; k++) {
        v[k].x *= g1v.x; v[k].y *= g1v.y; v[k].z *= g1v.z; v[k].w *= g1v.w;
        s2 += v[k].x + v[k].y + v[k].z + v[k].w;
        m2 = fmaxf(m2, fmaxf(fmaxf(v[k].x, v[k].y), fmaxf(v[k].z, v[k].w)));
    }

    // ---- g2 per patch: reduce over the 32 threads sharing each patch ----
    float* p2s = uni;                    // [group=t>>3][patch=t&7] == index t
    float* p2m = uni + 256;
    p2s[t] = s2;
    p2m[t] = m2;
    __syncthreads();
    if (t < 8) {
        float s = 0.f, mx = -3.4e38f;
        #pragma unroll
        for (int g = 0; g < 32; g++) {
            s += p2s[g * 8 + t];
            mx = fmaxf(mx, p2m[g * 8 + t]);
        }
        g2s[t] = sigm(c2w0 * (s * (1.0f / 1024.0f)) + c2w1 * mx + c2b0);
    }
    __syncthreads();
    const float g2 = g2s[patch];

    // ---- apply g2 and store (same coalesced pattern as load) ----
    #pragma unroll
    for (int k = 0; k < 8; k++) {
        float4 a = v[k];
        a.x *= g2; a.y *= g2; a.z *= g2; a.w *= g2;
        const int c = cb + 8 * k;
        *(float4*)(ob + (size_t)c * plane + rowbase) = a;
    }
}

extern "C" void kernel_launch(void* const* d_in, const int* in_sizes, int n_in,
                              void* d_out, int out_size) {
    const float* x    = (const float*)d_in[0];
    const float* fc_w = (const float*)d_in[1];
    const float* fc_b = (const float*)d_in[2];
    const float* c1w  = (const float*)d_in[3];
    const float* c1b  = (const float*)d_in[4];
    const float* c2w  = (const float*)d_in[5];
    const float* c2b  = (const float*)d_in[6];
    float* out = (float*)d_out;

    // 4096 blocks: 8 batches x 64 patch-rows x 8 groups of 8 patches
    ciam_fused_kernel<<<4096, THREADS>>>(x, fc_w, fc_b, c1w, c1b, c2w, c2b, out);
}

// round 3
// speedup vs baseline: 1.1646x; 1.1646x over previous
#include <cuda_runtime.h>

// Problem constants (fixed by the dataset instance)
#define Bc 8
#define Cc 64
#define Hc 256
#define Wc 256
// size = 4 -> 64x64 patches of 4x4; each block handles 16 patches
#define THREADS 256

__device__ __forceinline__ float sigm(float x) {
    return 1.0f / (1.0f + __expf(-x));
}

__global__ __launch_bounds__(THREADS, 2)
void ciam_fused_kernel(const float* __restrict__ x,
                       const float* __restrict__ fc_w,
                       const float* __restrict__ fc_b,
                       const float* __restrict__ c1w,
                       const float* __restrict__ c1b,
                       const float* __restrict__ c2w,
                       const float* __restrict__ c2b,
                       float* __restrict__ out)
{
    // ---- block / thread decomposition ----
    const int blk = blockIdx.x;          // 0..2047
    const int pwg = blk & 3;             // 16-patch group along W
    const int ph  = (blk >> 2) & 63;     // patch row
    const int b   = blk >> 8;            // batch

    const int t     = threadIdx.x;
    const int patch = t & 15;            // local patch id (pw = pwg*16 + patch)
    const int r     = (t >> 4) & 3;      // row within patch
    const int cb    = t >> 6;            // channel base (c = cb + 4k)

    // ---- shared memory (~43.3 KB) ----
    __shared__ float wS[64 * 68];        // fc_w rows, stride 68 (16B-aligned, banks 4c)
    __shared__ float mxT[64 * 16];       // per-patch channel maxes, k-major [k][p]
    __shared__ float msm[64 * 16];       // channel-attention m[c][p], p contiguous
    __shared__ float g1s[64 * 4];        // g1[(r,patch)][px]
    __shared__ float fcbS[64];
    __shared__ float g2s[16];
    __shared__ float uni[4224];          // pm[4r][64c][16p] (row stride 1040) -> gsum/gmax/p2s/p2m

    // ---- scalar weights ----
    const float c1w0 = __ldg(c1w), c1w1 = __ldg(c1w + 1), c1b0 = __ldg(c1b);
    const float c2w0 = __ldg(c2w), c2w1 = __ldg(c2w + 1), c2b0 = __ldg(c2b);

    // ---- load tile into registers (16 x float4, coalesced) ----
    const size_t plane = (size_t)Hc * Wc;
    const float* xb = x + (size_t)b * Cc * plane;
    float* ob = out + (size_t)b * Cc * plane;
    const int rowbase = (ph * 4 + r) * Wc + pwg * 64 + patch * 4;

    float4 v[16];
    #pragma unroll
    for (int k = 0; k < 16; k++) {
        const int c = cb + 4 * k;
        v[k] = *(const float4*)(xb + (size_t)c * plane + rowbase);
    }

    // ---- stage fc_w -> smem (stride 68), fc_b -> smem ----
    #pragma unroll
    for (int i = 0; i < 4; i++) {
        const int j  = t + 256 * i;      // float4 chunk id, 0..1023
        const int c  = j >> 4;
        const int k4 = j & 15;
        float4 wv = *(const float4*)(fc_w + c * 64 + k4 * 4);
        *(float4*)(wS + c * 68 + k4 * 4) = wv;
    }
    if (t < 64) fcbS[t] = fc_b[t];

    // ---- per-(c, r, patch) row max -> pm (row stride 1040: conflict-free) ----
    float* pm = uni;                     // [r][c][p] = r*1040 + c*16 + p
    #pragma unroll
    for (int k = 0; k < 16; k++) {
        float4 a = v[k];
        float rm = fmaxf(fmaxf(a.x, a.y), fmaxf(a.z, a.w));
        pm[r * 1040 + (cb + 4 * k) * 16 + patch] = rm;
    }
    __syncthreads();

    // ---- reduce over r -> mxT[k][p] (k-major) ----
    {
        const int p  = t & 15;
        const int cB = t >> 4;           // 0..15
        #pragma unroll
        for (int j = 0; j < 4; j++) {
            const int c = cB + 16 * j;   // conflict-free: addr = c*16+p, c in {cB, cB+16,..}
            float m0 = pm[0 * 1040 + c * 16 + p];
            m0 = fmaxf(m0, pm[1 * 1040 + c * 16 + p]);
            m0 = fmaxf(m0, pm[2 * 1040 + c * 16 + p]);
            m0 = fmaxf(m0, pm[3 * 1040 + c * 16 + p]);
            mxT[c * 16 + p] = m0;        // mxT[k][p] with k == c index of the max vector
        }
    }
    __syncthreads();

    // ---- matvec: m[c][p] = sigmoid(sum_k w[c][k]*mx[k][p] + b[c]) ----
    // thread: c = t>>2 (one row), pq = t&3 (one float4 of patches)
    {
        const int c  = t >> 2;
        const int pq = t & 3;
        float4 acc = make_float4(0.f, 0.f, 0.f, 0.f);
        #pragma unroll
        for (int kc = 0; kc < 16; kc++) {
            const float4 w4 = *(const float4*)(wS + c * 68 + kc * 4);   // 1 wf/warp
            const float4 m0 = *(const float4*)(mxT + (kc * 4 + 0) * 16 + pq * 4);
            const float4 m1 = *(const float4*)(mxT + (kc * 4 + 1) * 16 + pq * 4);
            const float4 m2 = *(const float4*)(mxT + (kc * 4 + 2) * 16 + pq * 4);
            const float4 m3 = *(const float4*)(mxT + (kc * 4 + 3) * 16 + pq * 4);
            acc.x += w4.x * m0.x + w4.y * m1.x + w4.z * m2.x + w4.w * m3.x;
            acc.y += w4.x * m0.y + w4.y * m1.y + w4.z * m2.y + w4.w * m3.y;
            acc.z += w4.x * m0.z + w4.y * m1.z + w4.z * m2.z + w4.w * m3.z;
            acc.w += w4.x * m0.w + w4.y * m1.w + w4.z * m2.w + w4.w * m3.w;
        }
        const float bc = fcbS[c];
        float4 mres;
        mres.x = sigm(acc.x + bc);
        mres.y = sigm(acc.y + bc);
        mres.z = sigm(acc.z + bc);
        mres.w = sigm(acc.w + bc);
        *(float4*)(msm + c * 16 + pq * 4) = mres;
    }
    __syncthreads();

    // ---- apply channel attention; per-(patch,pixel) partials over 16 channels ----
    float4 ps  = make_float4(0.f, 0.f, 0.f, 0.f);
    float4 pmx = make_float4(-3.4e38f, -3.4e38f, -3.4e38f, -3.4e38f);
    #pragma unroll
    for (int k = 0; k < 16; k++) {
        const float m = msm[(cb + 4 * k) * 16 + patch];
        v[k].x *= m; v[k].y *= m; v[k].z *= m; v[k].w *= m;
        ps.x += v[k].x; ps.y += v[k].y; ps.z += v[k].z; ps.w += v[k].w;
        pmx.x = fmaxf(pmx.x, v[k].x); pmx.y = fmaxf(pmx.y, v[k].y);
        pmx.z = fmaxf(pmx.z, v[k].z); pmx.w = fmaxf(pmx.w, v[k].w);
    }
    float* gsum = uni;                   // [cb][rp][px] : cb*256 + rp*4 + px
    float* gmax = uni + 1024;
    const int rp = t & 63;               // (r, patch)
    *(float4*)(gsum + cb * 256 + rp * 4) = ps;
    *(float4*)(gmax + cb * 256 + rp * 4) = pmx;
    __syncthreads();

    // ---- g1 per (patch, pixel): reduce over the 4 channel-base groups ----
    {
        float s  = gsum[t] + gsum[256 + t] + gsum[512 + t] + gsum[768 + t];
        float mx = fmaxf(fmaxf(gmax[t], gmax[256 + t]), fmaxf(gmax[512 + t], gmax[768 + t]));
        g1s[t] = sigm(c1w0 * (s * (1.0f / 64.0f)) + c1w1 * mx + c1b0);
    }
    __syncthreads();

    // ---- apply g1; per-patch partials over this thread's 64 values ----
    const float4 g1v = *(const float4*)(g1s + rp * 4);
    float s2 = 0.f, m2 = -3.4e38f;
    #pragma unroll
    for (int k = 0; k < 16; k++) {
        v[k].x *= g1v.x; v[k].y *= g1v.y; v[k].z *= g1v.z; v[k].w *= g1v.w;
        s2 += v[k].x + v[k].y + v[k].z + v[k].w;
        m2 = fmaxf(m2, fmaxf(fmaxf(v[k].x, v[k].y), fmaxf(v[k].z, v[k].w)));
    }

    // ---- g2 per patch: reduce over the 16 threads sharing each patch ----
    float* p2s = uni + 2048;             // [group=t>>4][patch=t&15] == index t
    float* p2m = uni + 2048 + 256;
    p2s[t] = s2;
    p2m[t] = m2;
    __syncthreads();
    if (t < 16) {
        float s = 0.f, mx = -3.4e38f;
        #pragma unroll
        for (int g = 0; g < 16; g++) {
            s += p2s[g * 16 + t];
            mx = fmaxf(mx, p2m[g * 16 + t]);
        }
        g2s[t] = sigm(c2w0 * (s * (1.0f / 1024.0f)) + c2w1 * mx + c2b0);
    }
    __syncthreads();
    const float g2 = g2s[patch];

    // ---- apply g2 and store (same coalesced pattern as load) ----
    #pragma unroll
    for (int k = 0; k < 16; k++) {
        float4 a = v[k];
        a.x *= g2; a.y *= g2; a.z *= g2; a.w *= g2;
        const int c = cb + 4 * k;
        *(float4*)(ob + (size_t)c * plane + rowbase) = a;
    }
}

extern "C" void kernel_launch(void* const* d_in, const int* in_sizes, int n_in,
                              void* d_out, int out_size) {
    const float* x    = (const float*)d_in[0];
    const float* fc_w = (const float*)d_in[1];
    const float* fc_b = (const float*)d_in[2];
    const float* c1w  = (const float*)d_in[3];
    const float* c1b  = (const float*)d_in[4];
    const float* c2w  = (const float*)d_in[5];
    const float* c2b  = (const float*)d_in[6];
    float* out = (float*)d_out;

    // 2048 blocks: 8 batches x 64 patch-rows x 4 groups of 16 patches
    ciam_fused_kernel<<<2048, THREADS>>>(x, fc_w, fc_b, c1w, c1b, c2w, c2b, out);
}